// round 2
// baseline (speedup 1.0000x reference)
#include <cuda_runtime.h>
#include <cstdint>

// Problem constants (fixed shapes for this problem instance)
#define Lc     2048
#define Bc     2
#define Hc     32
#define Pc     64
#define Nc     128
#define DPROJ  4384      // 2*d_inner + 2*dstate + nheads
#define DCONVC 2304      // d_inner + 2*dstate
#define DINNER 2048

// ---------------- scratch (static device globals; no runtime alloc) ---------
// x / gate planes: [q = (b*H + h)*2 + pchunk][t][32]
__device__ __align__(16) float g_x [(size_t)Bc * Hc * 2 * Lc * 32];   // 33.5 MB
__device__ __align__(16) float g_g [(size_t)Bc * Hc * 2 * Lc * 32];   // 33.5 MB
__device__ __align__(16) float g_B [(size_t)Bc * Lc * Nc];            // 2 MB
__device__ __align__(16) float g_C [(size_t)Bc * Lc * Nc];            // 2 MB
__device__ __align__(16) float g_dtA[(size_t)Bc * Hc * Lc * 2];       // 1 MB

// ---------------- packed f32x2 helpers --------------------------------------
__device__ __forceinline__ uint64_t pk2(float lo, float hi) {
    uint64_t r;
    asm("mov.b64 %0, {%1,%2};" : "=l"(r) : "f"(lo), "f"(hi));
    return r;
}
__device__ __forceinline__ void unpk2(uint64_t v, float& lo, float& hi) {
    asm("mov.b64 {%0,%1}, %2;" : "=f"(lo), "=f"(hi) : "l"(v));
}
__device__ __forceinline__ uint64_t f2fma(uint64_t a, uint64_t b, uint64_t c) {
    uint64_t d;
    asm("fma.rn.f32x2 %0, %1, %2, %3;" : "=l"(d) : "l"(a), "l"(b), "l"(c));
    return d;
}
__device__ __forceinline__ uint64_t f2mul(uint64_t a, uint64_t b) {
    uint64_t d;
    asm("mul.rn.f32x2 %0, %1, %2;" : "=l"(d) : "l"(a), "l"(b));
    return d;
}
__device__ __forceinline__ void cpa16(void* sm, const void* gm) {
    unsigned sa = (unsigned)__cvta_generic_to_shared(sm);
    asm volatile("cp.async.cg.shared.global [%0], [%1], 16;" :: "r"(sa), "l"(gm));
}
__device__ __forceinline__ float fast_silu(float v) {
    return v * (1.f / (1.f + __expf(-v)));
}

// ---------------- pre-pass: conv + SiLU + dt/dA + gate, routed to scratch ---
__global__ void prepass_kernel(const float* __restrict__ zx,
                               const float* __restrict__ cw,
                               const float* __restrict__ cb,
                               const float* __restrict__ dt_bias,
                               const float* __restrict__ a_log,
                               const float* __restrict__ dt_scale) {
    int bt  = blockIdx.x;            // b*L + t
    int b   = bt >> 11;
    int t   = bt & (Lc - 1);
    int idx = blockIdx.y * 256 + threadIdx.x;   // "work channel"
    if (idx >= DPROJ) return;

    const float* row = zx + (size_t)bt * DPROJ;

    if (idx < DINNER) {
        // gate path: g = silu(z)
        float z = row[idx];
        int h = idx >> 6, p = idx & 63;
        g_g[(((((size_t)b * Hc + h) * 2 + (p >> 5)) * Lc) + t) * 32 + (p & 31)] = fast_silu(z);
    } else if (idx < DINNER + DCONVC) {
        // depthwise causal conv (k=4) + bias + silu; channel column in zx == idx
        int cc = idx - DINNER;
        float acc = cb[cc];
        const float* w = cw + cc * 4;
        #pragma unroll
        for (int i = 0; i < 4; ++i) {
            int l2 = t - 3 + i;
            if (l2 >= 0) acc += w[i] * zx[((size_t)(b * Lc + l2)) * DPROJ + idx];
        }
        float v = fast_silu(acc);
        if (cc < DINNER) {
            int h = cc >> 6, p = cc & 63;
            g_x[(((((size_t)b * Hc + h) * 2 + (p >> 5)) * Lc) + t) * 32 + (p & 31)] = v;
        } else if (cc < DINNER + Nc) {
            g_B[((size_t)(b * Lc + t)) * Nc + (cc - DINNER)] = v;
        } else {
            g_C[((size_t)(b * Lc + t)) * Nc + (cc - DINNER - Nc)] = v;
        }
    } else {
        // dt path: one per head
        int h = idx - (DINNER + DCONVC);
        float v  = row[DPROJ - Hc + h] * dt_scale[h] + dt_bias[h];
        float dt = (v > 20.f) ? v : log1pf(expf(v));
        dt = fminf(fmaxf(dt, 0.f), 100.f);
        float A  = -expf(a_log[h]);
        float dA = expf(dt * A);
        size_t o = ((size_t)(b * Hc + h) * Lc + t) * 2;
        g_dtA[o]     = dt;
        g_dtA[o + 1] = dA;
    }
}

// ---------------- scan kernel -----------------------------------------------
// grid = 128 blocks: (b,h,pchunk).  block = 128 threads: 8 p-groups x 16 n-slices.
// Thread owns 4 p x 8 n = 32 state values as 16 packed f32x2 (s2[pp][4]).
#define NSTAGE 4
#define SSTEPS 8
#define NITER  (Lc / SSTEPS)   // 256

__global__ void __launch_bounds__(128, 1)
scan_kernel(const float* __restrict__ d_param,
            const float* __restrict__ init_state,
            float* __restrict__ out) {
    const int bid = blockIdx.x;
    const int b  = bid >> 6;
    const int h  = (bid >> 1) & 31;
    const int pc = bid & 1;
    const int tid = threadIdx.x;
    const int pg  = tid >> 4;      // p-group 0..7 (4 p each)
    const int jn  = tid & 15;      // n-slice 0..15 (8 n each)

    __shared__ __align__(16) float sB  [NSTAGE][SSTEPS][Nc];
    __shared__ __align__(16) float sC  [NSTAGE][SSTEPS][Nc];
    __shared__ __align__(16) float sX  [NSTAGE][SSTEPS][32];
    __shared__ __align__(16) float sG  [NSTAGE][SSTEPS][32];
    __shared__ __align__(16) float sdtA[NSTAGE][SSTEPS][2];

    const int q = (b * Hc + h) * 2 + pc;
    const float4* gB   = (const float4*)(g_B + (size_t)b * Lc * Nc);
    const float4* gC   = (const float4*)(g_C + (size_t)b * Lc * Nc);
    const float4* gX   = (const float4*)(g_x + (size_t)q * Lc * 32);
    const float4* gG   = (const float4*)(g_g + (size_t)q * Lc * 32);
    const float4* gdtA = (const float4*)(g_dtA + (size_t)(b * Hc + h) * Lc * 2);

    // per stage: B/C = 256 float4 each, X/G = 64 float4, dtA = 4 float4
    auto issue_stage = [&](int k, int buf) {
        const float4* srcB = gB + (size_t)k * 256;
        const float4* srcC = gC + (size_t)k * 256;
        #pragma unroll
        for (int r = 0; r < 2; ++r) {
            cpa16(&sB[buf][0][(tid + r * 128) * 4], srcB + tid + r * 128);
            cpa16(&sC[buf][0][(tid + r * 128) * 4], srcC + tid + r * 128);
        }
        if (tid < 64) {
            cpa16(&sX[buf][0][tid * 4], gX + (size_t)k * 64 + tid);
            cpa16(&sG[buf][0][tid * 4], gG + (size_t)k * 64 + tid);
        }
        if (tid < 4) cpa16(&sdtA[buf][0][tid * 4], gdtA + (size_t)k * 4 + tid);
    };

    // init state from initial_state[b,h,p,:]; thread p = pc*32 + pg*4 + pp, n = jn*8..jn*8+7
    uint64_t s2[4][4];
    #pragma unroll
    for (int pp = 0; pp < 4; ++pp) {
        int p = pc * 32 + pg * 4 + pp;
        const float4* ist = (const float4*)(init_state +
                            ((size_t)((b * Hc + h) * Pc + p)) * Nc + jn * 8);
        float4 v0 = ist[0], v1 = ist[1];
        s2[pp][0] = pk2(v0.x, v0.y);
        s2[pp][1] = pk2(v0.z, v0.w);
        s2[pp][2] = pk2(v1.x, v1.y);
        s2[pp][3] = pk2(v1.z, v1.w);
    }
    const float Dh = d_param[h];

    // prologue: fill the ring
    #pragma unroll
    for (int s = 0; s < NSTAGE; ++s) {
        issue_stage(s, s);
        asm volatile("cp.async.commit_group;");
    }

    float* outbase = out + (size_t)b * Lc * DINNER + h * 64 + pc * 32 + pg * 4;

    for (int k = 0; k < NITER; ++k) {
        asm volatile("cp.async.wait_group %0;" :: "n"(NSTAGE - 1));
        __syncthreads();
        const int buf = k & (NSTAGE - 1);

        #pragma unroll
        for (int u = 0; u < SSTEPS; ++u) {
            float2 da = *(const float2*)&sdtA[buf][u][0];     // {dt, dA} broadcast
            float4 xv = *(const float4*)&sX[buf][u][pg * 4];  // 4 p-values of x
            uint64_t dA2 = pk2(da.y, da.y);
            const ulonglong2* Bp = (const ulonglong2*)&sB[buf][u][jn * 8];
            const ulonglong2* Cp = (const ulonglong2*)&sC[buf][u][jn * 8];
            ulonglong2 bA = Bp[0], bB = Bp[1];
            ulonglong2 cA = Cp[0], cB = Cp[1];

            float y[4];
            #pragma unroll
            for (int pp = 0; pp < 4; ++pp) {
                float xp = (pp == 0) ? xv.x : (pp == 1) ? xv.y : (pp == 2) ? xv.z : xv.w;
                float dtx = da.x * xp;
                uint64_t dtx2 = pk2(dtx, dtx);
                s2[pp][0] = f2fma(dA2, s2[pp][0], f2mul(dtx2, bA.x));
                s2[pp][1] = f2fma(dA2, s2[pp][1], f2mul(dtx2, bA.y));
                s2[pp][2] = f2fma(dA2, s2[pp][2], f2mul(dtx2, bB.x));
                s2[pp][3] = f2fma(dA2, s2[pp][3], f2mul(dtx2, bB.y));
                uint64_t acc = f2mul(s2[pp][0], cA.x);
                acc = f2fma(s2[pp][1], cA.y, acc);
                acc = f2fma(s2[pp][2], cB.x, acc);
                acc = f2fma(s2[pp][3], cB.y, acc);
                float lo, hi; unpk2(acc, lo, hi);
                y[pp] = lo + hi;
            }
            // reduce over 16 n-slices (lanes jn = 0..15 within each half-warp)
            #pragma unroll
            for (int off = 1; off < 16; off <<= 1) {
                #pragma unroll
                for (int pp = 0; pp < 4; ++pp)
                    y[pp] += __shfl_xor_sync(0xffffffffu, y[pp], off);
            }
            if (jn == 0) {
                float4 gv = *(const float4*)&sG[buf][u][pg * 4];
                int t = k * SSTEPS + u;
                float4 o;
                o.x = (y[0] + Dh * xv.x) * gv.x;
                o.y = (y[1] + Dh * xv.y) * gv.y;
                o.z = (y[2] + Dh * xv.z) * gv.z;
                o.w = (y[3] + Dh * xv.w) * gv.w;
                *(float4*)(outbase + (size_t)t * DINNER) = o;
            }
        }
        __syncthreads();
        int kn = k + NSTAGE;
        if (kn < NITER) issue_stage(kn, buf);
        asm volatile("cp.async.commit_group;");
    }
}

// ---------------- launch -----------------------------------------------------
extern "C" void kernel_launch(void* const* d_in, const int* in_sizes, int n_in,
                              void* d_out, int out_size) {
    const float* zxbcdt     = (const float*)d_in[0];
    const float* conv_w     = (const float*)d_in[1];
    const float* conv_b     = (const float*)d_in[2];
    const float* dt_bias    = (const float*)d_in[3];
    const float* a_log      = (const float*)d_in[4];
    const float* d_param    = (const float*)d_in[5];
    const float* dt_scale   = (const float*)d_in[6];
    const float* init_state = (const float*)d_in[7];
    float* out = (float*)d_out;

    dim3 pg(Bc * Lc, (DPROJ + 255) / 256);
    prepass_kernel<<<pg, 256>>>(zxbcdt, conv_w, conv_b, dt_bias, a_log, dt_scale);
    scan_kernel<<<Bc * Hc * 2, 128>>>(d_param, init_state, out);
}

// round 3
// speedup vs baseline: 1.5200x; 1.5200x over previous
#include <cuda_runtime.h>
#include <cstdint>

// Problem constants (fixed shapes for this problem instance)
#define Lc     2048
#define Bc     2
#define Hc     32
#define Pc     64
#define Nc     128
#define DPROJ  4384      // 2*d_inner + 2*dstate + nheads
#define DCONVC 2304      // d_inner + 2*dstate
#define DINNER 2048

// ---------------- scratch (static device globals; no runtime alloc) ---------
__device__ __align__(16) float g_x [(size_t)Bc * Hc * 2 * Lc * 32];   // 33.5 MB
__device__ __align__(16) float g_g [(size_t)Bc * Hc * 2 * Lc * 32];   // 33.5 MB
__device__ __align__(16) float g_B [(size_t)Bc * Lc * Nc];            // 2 MB
__device__ __align__(16) float g_C [(size_t)Bc * Lc * Nc];            // 2 MB
__device__ __align__(16) float g_dtA[(size_t)Bc * Hc * Lc * 2];       // 1 MB

// ---------------- packed f32x2 helpers --------------------------------------
__device__ __forceinline__ uint64_t pk2(float lo, float hi) {
    uint64_t r;
    asm("mov.b64 %0, {%1,%2};" : "=l"(r) : "f"(lo), "f"(hi));
    return r;
}
__device__ __forceinline__ void unpk2(uint64_t v, float& lo, float& hi) {
    asm("mov.b64 {%0,%1}, %2;" : "=f"(lo), "=f"(hi) : "l"(v));
}
__device__ __forceinline__ uint64_t f2fma(uint64_t a, uint64_t b, uint64_t c) {
    uint64_t d;
    asm("fma.rn.f32x2 %0, %1, %2, %3;" : "=l"(d) : "l"(a), "l"(b), "l"(c));
    return d;
}
__device__ __forceinline__ uint64_t f2mul(uint64_t a, uint64_t b) {
    uint64_t d;
    asm("mul.rn.f32x2 %0, %1, %2;" : "=l"(d) : "l"(a), "l"(b));
    return d;
}
__device__ __forceinline__ void cpa16(void* sm, const void* gm) {
    unsigned sa = (unsigned)__cvta_generic_to_shared(sm);
    asm volatile("cp.async.cg.shared.global [%0], [%1], 16;" :: "r"(sa), "l"(gm));
}
__device__ __forceinline__ float fast_silu(float v) {
    return v * (1.f / (1.f + __expf(-v)));
}

// ---------------- pre-pass: conv + SiLU + dt/dA + gate, routed to scratch ---
__global__ void prepass_kernel(const float* __restrict__ zx,
                               const float* __restrict__ cw,
                               const float* __restrict__ cb,
                               const float* __restrict__ dt_bias,
                               const float* __restrict__ a_log,
                               const float* __restrict__ dt_scale) {
    int bt  = blockIdx.x;            // b*L + t
    int b   = bt >> 11;
    int t   = bt & (Lc - 1);
    int idx = blockIdx.y * 256 + threadIdx.x;   // "work channel"
    if (idx >= DPROJ) return;

    const float* row = zx + (size_t)bt * DPROJ;

    if (idx < DINNER) {
        float z = row[idx];
        int h = idx >> 6, p = idx & 63;
        g_g[(((((size_t)b * Hc + h) * 2 + (p >> 5)) * Lc) + t) * 32 + (p & 31)] = fast_silu(z);
    } else if (idx < DINNER + DCONVC) {
        int cc = idx - DINNER;
        float acc = cb[cc];
        const float* w = cw + cc * 4;
        #pragma unroll
        for (int i = 0; i < 4; ++i) {
            int l2 = t - 3 + i;
            if (l2 >= 0) acc += w[i] * zx[((size_t)(b * Lc + l2)) * DPROJ + idx];
        }
        float v = fast_silu(acc);
        if (cc < DINNER) {
            int h = cc >> 6, p = cc & 63;
            g_x[(((((size_t)b * Hc + h) * 2 + (p >> 5)) * Lc) + t) * 32 + (p & 31)] = v;
        } else if (cc < DINNER + Nc) {
            g_B[((size_t)(b * Lc + t)) * Nc + (cc - DINNER)] = v;
        } else {
            g_C[((size_t)(b * Lc + t)) * Nc + (cc - DINNER - Nc)] = v;
        }
    } else {
        int h = idx - (DINNER + DCONVC);
        float v  = row[DPROJ - Hc + h] * dt_scale[h] + dt_bias[h];
        float dt = (v > 20.f) ? v : log1pf(expf(v));
        dt = fminf(fmaxf(dt, 0.f), 100.f);
        float A  = -expf(a_log[h]);
        float dA = expf(dt * A);
        size_t o = ((size_t)(b * Hc + h) * Lc + t) * 2;
        g_dtA[o]     = dt;
        g_dtA[o + 1] = dA;
    }
}

// ---------------- scan kernel -----------------------------------------------
// grid = 128 blocks: (b,h,pchunk).  block = 128 threads: 8 p-groups x 16 n-slices.
// Thread owns 4 p x 8 n state.  Per 8-step tile: compute phase (pure FMA) writes
// 32 register partials; reduction phase does 4 SHFL/step with 8-way ILP.
#define NSTAGE 4
#define SSTEPS 8
#define NITER  (Lc / SSTEPS)   // 256

__global__ void __launch_bounds__(128, 1)
scan_kernel(const float* __restrict__ d_param,
            const float* __restrict__ init_state,
            float* __restrict__ out) {
    const int bid = blockIdx.x;
    const int b  = bid >> 6;
    const int h  = (bid >> 1) & 31;
    const int pc = bid & 1;
    const int tid = threadIdx.x;
    const int pg  = tid >> 4;      // p-group 0..7 (4 p each)
    const int jn  = tid & 15;      // n-slice 0..15 (8 n each)
    const int bit0 = jn & 1;
    const int bit1 = (jn >> 1) & 1;

    __shared__ __align__(16) float sB  [NSTAGE][SSTEPS][Nc];
    __shared__ __align__(16) float sC  [NSTAGE][SSTEPS][Nc];
    __shared__ __align__(16) float sX  [NSTAGE][SSTEPS][32];
    __shared__ __align__(16) float sG  [NSTAGE][SSTEPS][32];
    __shared__ __align__(16) float sdtA[NSTAGE][SSTEPS][2];

    const int q = (b * Hc + h) * 2 + pc;
    const float4* gB   = (const float4*)(g_B + (size_t)b * Lc * Nc);
    const float4* gC   = (const float4*)(g_C + (size_t)b * Lc * Nc);
    const float4* gX   = (const float4*)(g_x + (size_t)q * Lc * 32);
    const float4* gG   = (const float4*)(g_g + (size_t)q * Lc * 32);
    const float4* gdtA = (const float4*)(g_dtA + (size_t)(b * Hc + h) * Lc * 2);

    auto issue_stage = [&](int k, int buf) {
        const float4* srcB = gB + (size_t)k * 256;
        const float4* srcC = gC + (size_t)k * 256;
        #pragma unroll
        for (int r = 0; r < 2; ++r) {
            cpa16(&sB[buf][0][(tid + r * 128) * 4], srcB + tid + r * 128);
            cpa16(&sC[buf][0][(tid + r * 128) * 4], srcC + tid + r * 128);
        }
        if (tid < 64) {
            cpa16(&sX[buf][0][tid * 4], gX + (size_t)k * 64 + tid);
            cpa16(&sG[buf][0][tid * 4], gG + (size_t)k * 64 + tid);
        }
        if (tid < 4) cpa16(&sdtA[buf][0][tid * 4], gdtA + (size_t)k * 4 + tid);
    };

    // init state; thread p = pc*32 + pg*4 + pp, n = jn*8..jn*8+7
    uint64_t s2[4][4];
    #pragma unroll
    for (int pp = 0; pp < 4; ++pp) {
        int p = pc * 32 + pg * 4 + pp;
        const float4* ist = (const float4*)(init_state +
                            ((size_t)((b * Hc + h) * Pc + p)) * Nc + jn * 8);
        float4 v0 = ist[0], v1 = ist[1];
        s2[pp][0] = pk2(v0.x, v0.y);
        s2[pp][1] = pk2(v0.z, v0.w);
        s2[pp][2] = pk2(v1.x, v1.y);
        s2[pp][3] = pk2(v1.z, v1.w);
    }
    const float Dh = d_param[h];

    #pragma unroll
    for (int s = 0; s < NSTAGE; ++s) {
        issue_stage(s, s);
        asm volatile("cp.async.commit_group;");
    }

    // writer lanes: jn < 4 write p = pc*32 + pg*4 + jn
    float* outw = out + (size_t)b * Lc * DINNER + h * 64 + pc * 32 + pg * 4 + (jn & 3);

    for (int k = 0; k < NITER; ++k) {
        asm volatile("cp.async.wait_group %0;" :: "n"(NSTAGE - 1));
        __syncthreads();
        const int buf = k & (NSTAGE - 1);

        float pY[SSTEPS][4];

        // ---- compute phase: pure FMA stream, partials to registers ----
        #pragma unroll
        for (int u = 0; u < SSTEPS; ++u) {
            float2 da = *(const float2*)&sdtA[buf][u][0];
            float4 xv = *(const float4*)&sX[buf][u][pg * 4];
            uint64_t dA2 = pk2(da.y, da.y);
            const ulonglong2* Bp = (const ulonglong2*)&sB[buf][u][jn * 8];
            const ulonglong2* Cp = (const ulonglong2*)&sC[buf][u][jn * 8];
            ulonglong2 bA = Bp[0], bB = Bp[1];
            ulonglong2 cA = Cp[0], cB = Cp[1];

            #pragma unroll
            for (int pp = 0; pp < 4; ++pp) {
                float xp = (pp == 0) ? xv.x : (pp == 1) ? xv.y : (pp == 2) ? xv.z : xv.w;
                float dtx = da.x * xp;
                uint64_t dtx2 = pk2(dtx, dtx);
                s2[pp][0] = f2fma(dA2, s2[pp][0], f2mul(dtx2, bA.x));
                s2[pp][1] = f2fma(dA2, s2[pp][1], f2mul(dtx2, bA.y));
                s2[pp][2] = f2fma(dA2, s2[pp][2], f2mul(dtx2, bB.x));
                s2[pp][3] = f2fma(dA2, s2[pp][3], f2mul(dtx2, bB.y));
                uint64_t acc = f2mul(s2[pp][0], cA.x);
                acc = f2fma(s2[pp][1], cA.y, acc);
                acc = f2fma(s2[pp][2], cB.x, acc);
                acc = f2fma(s2[pp][3], cB.y, acc);
                float lo, hi; unpk2(acc, lo, hi);
                float base = (jn == 0) ? Dh * xp : 0.f;   // fold D*x into jn==0 partial
                pY[u][pp] = (lo + hi) + base;
            }
        }

        // ---- reduction phase: 4 SHFL per step, all 8 steps independent ----
        #pragma unroll
        for (int u = 0; u < SSTEPS; ++u) {
            // round 1 (off=1): select-exchange, keep pp with (pp&1)==bit0
            float sA = bit0 ? pY[u][0] : pY[u][1];
            float sBv = bit0 ? pY[u][2] : pY[u][3];
            float rA = __shfl_xor_sync(0xffffffffu, sA, 1);
            float rB = __shfl_xor_sync(0xffffffffu, sBv, 1);
            float u0 = (bit0 ? pY[u][1] : pY[u][0]) + rA;   // pp = bit0
            float u1 = (bit0 ? pY[u][3] : pY[u][2]) + rB;   // pp = 2 + bit0
            // round 2 (off=2): keep pp = bit0 + 2*bit1
            float sC2 = bit1 ? u0 : u1;
            float rC = __shfl_xor_sync(0xffffffffu, sC2, 2);
            float w = (bit1 ? u1 : u0) + rC;                // lane jn holds pp = jn&3
            // rounds 3,4: plain butterfly over remaining n-groups
            w += __shfl_xor_sync(0xffffffffu, w, 4);
            w += __shfl_xor_sync(0xffffffffu, w, 8);

            if (jn < 4) {
                float gv = sG[buf][u][pg * 4 + jn];
                int t = k * SSTEPS + u;
                outw[(size_t)t * DINNER] = w * gv;
            }
        }

        __syncthreads();
        int kn = k + NSTAGE;
        if (kn < NITER) issue_stage(kn, buf);
        asm volatile("cp.async.commit_group;");
    }
}

// ---------------- launch -----------------------------------------------------
extern "C" void kernel_launch(void* const* d_in, const int* in_sizes, int n_in,
                              void* d_out, int out_size) {
    const float* zxbcdt     = (const float*)d_in[0];
    const float* conv_w     = (const float*)d_in[1];
    const float* conv_b     = (const float*)d_in[2];
    const float* dt_bias    = (const float*)d_in[3];
    const float* a_log      = (const float*)d_in[4];
    const float* d_param    = (const float*)d_in[5];
    const float* dt_scale   = (const float*)d_in[6];
    const float* init_state = (const float*)d_in[7];
    float* out = (float*)d_out;

    dim3 pg(Bc * Lc, (DPROJ + 255) / 256);
    prepass_kernel<<<pg, 256>>>(zxbcdt, conv_w, conv_b, dt_bias, a_log, dt_scale);
    scan_kernel<<<Bc * Hc * 2, 128>>>(d_param, init_state, out);
}